// round 1
// baseline (speedup 1.0000x reference)
#include <cuda_runtime.h>

// ---------------------------------------------------------------------------
// GIN encoder: 2 x [scatter-add aggregate -> MLP(64->64->64, tanh) -> tanh ->
// BatchNorm(train)] -> per-graph sum pool, concat -> [512, 128]
// ---------------------------------------------------------------------------

#define MAX_N 100000
#define DIM 64
#define BN_EPS 1e-5f

// Scratch (device globals: no runtime allocation allowed)
__device__ __align__(16) float g_agg[MAX_N * DIM];
__device__ __align__(16) float g_x0 [MAX_N * DIM];
__device__ __align__(16) float g_h  [MAX_N * DIM];
__device__ __align__(16) float g_stats[2 * DIM];   // [0:64) sum, [64:128) sumsq
__device__ __align__(16) float g_scale[DIM];
__device__ __align__(16) float g_shift[DIM];

// ---------------- packed f32x2 helpers (sm_100+) ---------------------------
static __device__ __forceinline__ unsigned long long ffma2(
    unsigned long long a, unsigned long long b, unsigned long long c) {
    unsigned long long d;
    asm("fma.rn.f32x2 %0, %1, %2, %3;" : "=l"(d) : "l"(a), "l"(b), "l"(c));
    return d;
}
static __device__ __forceinline__ unsigned long long pack2(float x, float y) {
    unsigned long long r;
    asm("mov.b64 %0, {%1, %2};" : "=l"(r) : "f"(x), "f"(y));
    return r;
}
static __device__ __forceinline__ float2 unpack2(unsigned long long v) {
    float2 f;
    asm("mov.b64 {%0, %1}, %2;" : "=f"(f.x), "=f"(f.y) : "l"(v));
    return f;
}

// ---------------- edge scatter-add -----------------------------------------
// agg[dst] += x[src], 16 threads per edge (float4 lanes)
__global__ void scatter_kernel(const int* __restrict__ ei,
                               const float* __restrict__ x, int E) {
    int t = blockIdx.x * blockDim.x + threadIdx.x;
    int total = E * 16;
    if (t >= total) return;
    int e = t >> 4;
    int c = t & 15;
    int s = __ldg(ei + e);
    int d = __ldg(ei + E + e);
    float4 v = reinterpret_cast<const float4*>(x)[s * 16 + c];
    float* a = g_agg + d * DIM + (c << 2);
    atomicAdd(a + 0, v.x);
    atomicAdd(a + 1, v.y);
    atomicAdd(a + 2, v.z);
    atomicAdd(a + 3, v.w);
}

// ---------------- fused MLP + tanh + BN stats ------------------------------
// One node per thread. Weights (2x 64x64) broadcast from shared; per-node row
// staged in shared (stride 65 to kill bank conflicts). f32x2 packed FMA.
static __device__ __forceinline__ void mlp_stage(float* row,
                                                 const float* Ws,
                                                 const float* bs) {
    unsigned long long acc[32];
    const unsigned long long* bu =
        reinterpret_cast<const unsigned long long*>(bs);
#pragma unroll
    for (int j = 0; j < 32; j++) acc[j] = bu[j];

    for (int k = 0; k < DIM; k++) {
        float xk = row[k];
        unsigned long long xx = pack2(xk, xk);
        const ulonglong2* Wp =
            reinterpret_cast<const ulonglong2*>(Ws + (k << 6));
#pragma unroll
        for (int j = 0; j < 16; j++) {
            ulonglong2 w = Wp[j];
            acc[2 * j + 0] = ffma2(xx, w.x, acc[2 * j + 0]);
            acc[2 * j + 1] = ffma2(xx, w.y, acc[2 * j + 1]);
        }
    }
#pragma unroll
    for (int j = 0; j < 32; j++) {
        float2 v = unpack2(acc[j]);
        row[2 * j + 0] = tanhf(v.x);
        row[2 * j + 1] = tanhf(v.y);
    }
}

#define MLP_SMEM_FLOATS (4096 + 4096 + 64 + 64 + 128 * 65)
#define MLP_SMEM_BYTES  (MLP_SMEM_FLOATS * 4)

__global__ __launch_bounds__(128) void mlp_kernel(
    const float* __restrict__ x,
    const float* __restrict__ W1, const float* __restrict__ b1,
    const float* __restrict__ W2, const float* __restrict__ b2, int N) {
    extern __shared__ float sm[];
    float* W1s  = sm;                 // 4096
    float* W2s  = sm + 4096;          // 4096
    float* b1s  = sm + 8192;          // 64
    float* b2s  = sm + 8256;          // 64
    float* rows = sm + 8320;          // 128 * 65

    int tid  = threadIdx.x;
    int node = blockIdx.x * 128 + tid;

    for (int i = tid; i < 4096; i += 128) {
        W1s[i] = W1[i];
        W2s[i] = W2[i];
    }
    if (tid < 64) {
        b1s[tid] = b1[tid];
        b2s[tid] = b2[tid];
    }

    float* myrow = rows + tid * 65;
    if (node < N) {
        const float4* x4 = reinterpret_cast<const float4*>(x);
        const float4* a4 = reinterpret_cast<const float4*>(g_agg);
#pragma unroll
        for (int c = 0; c < 16; c++) {
            float4 xv = x4[node * 16 + c];
            float4 av = a4[node * 16 + c];
            myrow[4 * c + 0] = xv.x + av.x;
            myrow[4 * c + 1] = xv.y + av.y;
            myrow[4 * c + 2] = xv.z + av.z;
            myrow[4 * c + 3] = xv.w + av.w;
        }
    } else {
#pragma unroll
        for (int c = 0; c < DIM; c++) myrow[c] = 0.0f;
    }
    __syncthreads();  // weights + rows ready

    if (node < N) {
        mlp_stage(myrow, W1s, b1s);  // tanh(h@W1+b1) written back into row
        mlp_stage(myrow, W2s, b2s);  // tanh(.@W2+b2)  (encoder tanh fused)
    }
    __syncthreads();

    // coalesced store of h to global
    int base = blockIdx.x * 128 * DIM;
    for (int i = tid; i < 128 * DIM; i += 128) {
        int r = i >> 6, c = i & 63;
        if (blockIdx.x * 128 + r < N) g_h[base + i] = rows[r * 65 + c];
    }

    // block-level BN statistics (invalid rows are zero -> contribute nothing)
    if (tid < 64) {
        float s = 0.0f;
        for (int r = 0; r < 128; r++) s += rows[r * 65 + tid];
        atomicAdd(&g_stats[tid], s);
    } else {
        int j = tid - 64;
        float s = 0.0f;
        for (int r = 0; r < 128; r++) {
            float v = rows[r * 65 + j];
            s += v * v;
        }
        atomicAdd(&g_stats[64 + j], s);
    }
}

// ---------------- BN finalize ----------------------------------------------
__global__ void finalize_kernel(const float* __restrict__ gamma,
                                const float* __restrict__ beta, float invN) {
    int j = threadIdx.x;  // 64 threads
    float mean = g_stats[j] * invN;
    float var  = g_stats[64 + j] * invN - mean * mean;
    float sc   = gamma[j] * rsqrtf(var + BN_EPS);
    g_scale[j] = sc;
    g_shift[j] = beta[j] - mean * sc;
}

// ---------------- BN apply + graph pooling ---------------------------------
__global__ void apply_pool_kernel(const int* __restrict__ batch,
                                  float* __restrict__ out,
                                  float* __restrict__ xstore,
                                  int col_off, int N) {
    int t = blockIdx.x * blockDim.x + threadIdx.x;
    if (t >= N * 16) return;
    int node = t >> 4;
    int c    = t & 15;
    float4 h  = reinterpret_cast<const float4*>(g_h)[t];
    float4 sc = reinterpret_cast<const float4*>(g_scale)[c];
    float4 sh = reinterpret_cast<const float4*>(g_shift)[c];
    float4 v;
    v.x = h.x * sc.x + sh.x;
    v.y = h.y * sc.y + sh.y;
    v.z = h.z * sc.z + sh.z;
    v.w = h.w * sc.w + sh.w;
    if (xstore) reinterpret_cast<float4*>(xstore)[t] = v;
    int g = __ldg(batch + node);
    float* o = out + g * 128 + col_off + (c << 2);
    atomicAdd(o + 0, v.x);
    atomicAdd(o + 1, v.y);
    atomicAdd(o + 2, v.z);
    atomicAdd(o + 3, v.w);
}

// ---------------------------------------------------------------------------
extern "C" void kernel_launch(void* const* d_in, const int* in_sizes, int n_in,
                              void* d_out, int out_size) {
    const float* x       = (const float*)d_in[0];
    const float* W1_0    = (const float*)d_in[1];
    const float* b1_0    = (const float*)d_in[2];
    const float* W2_0    = (const float*)d_in[3];
    const float* b2_0    = (const float*)d_in[4];
    const float* gamma_0 = (const float*)d_in[5];
    const float* beta_0  = (const float*)d_in[6];
    const float* W1_1    = (const float*)d_in[7];
    const float* b1_1    = (const float*)d_in[8];
    const float* W2_1    = (const float*)d_in[9];
    const float* b2_1    = (const float*)d_in[10];
    const float* gamma_1 = (const float*)d_in[11];
    const float* beta_1  = (const float*)d_in[12];
    const int*   ei      = (const int*)d_in[13];
    const int*   batch   = (const int*)d_in[14];

    int N = in_sizes[0] / DIM;
    int E = in_sizes[13] / 2;
    float* out = (float*)d_out;

    void *agg_p, *stats_p, *x0_p;
    cudaGetSymbolAddress(&agg_p, g_agg);
    cudaGetSymbolAddress(&stats_p, g_stats);
    cudaGetSymbolAddress(&x0_p, g_x0);

    cudaFuncSetAttribute(mlp_kernel,
                         cudaFuncAttributeMaxDynamicSharedMemorySize,
                         MLP_SMEM_BYTES);

    int scatter_blocks = (E * 16 + 255) / 256;
    int mlp_blocks     = (N + 127) / 128;
    int apply_blocks   = (N * 16 + 255) / 256;
    float invN = 1.0f / (float)N;

    cudaMemsetAsync(out, 0, (size_t)out_size * sizeof(float));

    // ---------------- layer 0 ----------------
    cudaMemsetAsync(agg_p, 0, (size_t)N * DIM * sizeof(float));
    cudaMemsetAsync(stats_p, 0, 2 * DIM * sizeof(float));
    scatter_kernel<<<scatter_blocks, 256>>>(ei, x, E);
    mlp_kernel<<<mlp_blocks, 128, MLP_SMEM_BYTES>>>(x, W1_0, b1_0, W2_0, b2_0, N);
    finalize_kernel<<<1, 64>>>(gamma_0, beta_0, invN);
    apply_pool_kernel<<<apply_blocks, 256>>>(batch, out, (float*)x0_p, 0, N);

    // ---------------- layer 1 ----------------
    cudaMemsetAsync(agg_p, 0, (size_t)N * DIM * sizeof(float));
    cudaMemsetAsync(stats_p, 0, 2 * DIM * sizeof(float));
    scatter_kernel<<<scatter_blocks, 256>>>(ei, (const float*)x0_p, E);
    mlp_kernel<<<mlp_blocks, 128, MLP_SMEM_BYTES>>>((const float*)x0_p,
                                                    W1_1, b1_1, W2_1, b2_1, N);
    finalize_kernel<<<1, 64>>>(gamma_1, beta_1, invN);
    apply_pool_kernel<<<apply_blocks, 256>>>(batch, out, nullptr, 64, N);
}

// round 2
// speedup vs baseline: 1.7995x; 1.7995x over previous
#include <cuda_runtime.h>

// ---------------------------------------------------------------------------
// GIN encoder: 2 x [CSR gather aggregate -> MLP(64->64->64, tanh) -> tanh ->
// BatchNorm(train)] -> per-graph sum pool (segmented; batch is sorted)
// ---------------------------------------------------------------------------

#define MAX_N 100000
#define MAX_E 1000000
#define DIM 64
#define BN_EPS 1e-5f
#define SCAN_BS 1024
#define POOL_CH 128

// Scratch (device globals: no runtime allocation allowed)
__device__ __align__(16) float g_hin[MAX_N * DIM];   // x + aggregate (MLP input)
__device__ __align__(16) float g_x0 [MAX_N * DIM];   // layer-0 BN output
__device__ __align__(16) float g_h  [MAX_N * DIM];   // pre-BN activations
__device__ __align__(16) float g_stats[2 * DIM];
__device__ __align__(16) float g_scale[DIM];
__device__ __align__(16) float g_shift[DIM];

__device__ int g_rowptr[MAX_N + 1];
__device__ int g_cursor[MAX_N + 1];   // counts, then fill cursors
__device__ int g_srcidx[MAX_E];
__device__ int g_bsums[(MAX_N + SCAN_BS - 1) / SCAN_BS + 1];

// ---------------- packed f32x2 helpers (sm_100+) ---------------------------
static __device__ __forceinline__ unsigned long long ffma2(
    unsigned long long a, unsigned long long b, unsigned long long c) {
    unsigned long long d;
    asm("fma.rn.f32x2 %0, %1, %2, %3;" : "=l"(d) : "l"(a), "l"(b), "l"(c));
    return d;
}
static __device__ __forceinline__ unsigned long long pack2(float x, float y) {
    unsigned long long r;
    asm("mov.b64 %0, {%1, %2};" : "=l"(r) : "f"(x), "f"(y));
    return r;
}
static __device__ __forceinline__ float2 unpack2(unsigned long long v) {
    float2 f;
    asm("mov.b64 {%0, %1}, %2;" : "=f"(f.x), "=f"(f.y) : "l"(v));
    return f;
}

// ---------------- CSR build ------------------------------------------------
__global__ void hist_kernel(const int* __restrict__ ei, int E) {
    int t = blockIdx.x * blockDim.x + threadIdx.x;
    if (t >= E) return;
    atomicAdd(&g_cursor[__ldg(ei + E + t)], 1);
}

__global__ void reduce_kernel(int N) {
    __shared__ int s[SCAN_BS];
    int i = threadIdx.x;
    int gi = blockIdx.x * SCAN_BS + i;
    s[i] = (gi < N) ? g_cursor[gi] : 0;
    __syncthreads();
    for (int off = SCAN_BS / 2; off > 0; off >>= 1) {
        if (i < off) s[i] += s[i + off];
        __syncthreads();
    }
    if (i == 0) g_bsums[blockIdx.x] = s[0];
}

__global__ void scan_bsums_kernel(int nb) {
    int run = 0;
    for (int b = 0; b < nb; b++) {
        int t = g_bsums[b];
        g_bsums[b] = run;
        run += t;
    }
}

__global__ void scan_final_kernel(int N) {
    __shared__ int s[SCAN_BS];
    int i = threadIdx.x;
    int gi = blockIdx.x * SCAN_BS + i;
    int val = (gi < N) ? g_cursor[gi] : 0;
    s[i] = val;
    __syncthreads();
    for (int off = 1; off < SCAN_BS; off <<= 1) {
        int t = (i >= off) ? s[i - off] : 0;
        __syncthreads();
        s[i] += t;
        __syncthreads();
    }
    int excl = s[i] - val;
    int rp = g_bsums[blockIdx.x] + excl;
    if (gi <= N) {
        g_rowptr[gi] = rp;
        if (gi < N) g_cursor[gi] = rp;
    }
}

__global__ void fill_kernel(const int* __restrict__ ei, int E) {
    int t = blockIdx.x * blockDim.x + threadIdx.x;
    if (t >= E) return;
    int s = __ldg(ei + t);
    int d = __ldg(ei + E + t);
    int pos = atomicAdd(&g_cursor[d], 1);
    g_srcidx[pos] = s;
}

// ---------------- aggregation (gather, no atomics) -------------------------
// 16 threads per node (float4 lanes); hout = x[node] + sum_{e} x[src[e]]
__global__ __launch_bounds__(128) void aggregate_kernel(
    const float* __restrict__ x, float* __restrict__ hout, int N) {
    int node = blockIdx.x * 8 + (threadIdx.x >> 4);
    int c = threadIdx.x & 15;
    if (node >= N) return;
    int beg = g_rowptr[node];
    int end = g_rowptr[node + 1];
    const float4* x4 = reinterpret_cast<const float4*>(x);
    float4 acc = x4[node * 16 + c];
    int e = beg;
    for (; e + 1 < end; e += 2) {
        int s0 = __ldg(g_srcidx + e);
        int s1 = __ldg(g_srcidx + e + 1);
        float4 v0 = x4[s0 * 16 + c];
        float4 v1 = x4[s1 * 16 + c];
        acc.x += v0.x + v1.x;
        acc.y += v0.y + v1.y;
        acc.z += v0.z + v1.z;
        acc.w += v0.w + v1.w;
    }
    if (e < end) {
        int s0 = __ldg(g_srcidx + e);
        float4 v0 = x4[s0 * 16 + c];
        acc.x += v0.x;
        acc.y += v0.y;
        acc.z += v0.z;
        acc.w += v0.w;
    }
    reinterpret_cast<float4*>(hout)[node * 16 + c] = acc;
}

// ---------------- fused MLP + tanh + BN stats ------------------------------
static __device__ __forceinline__ void mlp_stage(float* row,
                                                 const float* Ws,
                                                 const float* bs) {
    unsigned long long acc[32];
    const unsigned long long* bu =
        reinterpret_cast<const unsigned long long*>(bs);
#pragma unroll
    for (int j = 0; j < 32; j++) acc[j] = bu[j];

    for (int k = 0; k < DIM; k++) {
        float xk = row[k];
        unsigned long long xx = pack2(xk, xk);
        const ulonglong2* Wp =
            reinterpret_cast<const ulonglong2*>(Ws + (k << 6));
#pragma unroll
        for (int j = 0; j < 16; j++) {
            ulonglong2 w = Wp[j];
            acc[2 * j + 0] = ffma2(xx, w.x, acc[2 * j + 0]);
            acc[2 * j + 1] = ffma2(xx, w.y, acc[2 * j + 1]);
        }
    }
#pragma unroll
    for (int j = 0; j < 32; j++) {
        float2 v = unpack2(acc[j]);
        row[2 * j + 0] = tanhf(v.x);
        row[2 * j + 1] = tanhf(v.y);
    }
}

#define MLP_SMEM_FLOATS (4096 + 4096 + 64 + 64 + 128 * 65)
#define MLP_SMEM_BYTES  (MLP_SMEM_FLOATS * 4)

__global__ __launch_bounds__(128) void mlp_kernel(
    const float* __restrict__ hin,
    const float* __restrict__ W1, const float* __restrict__ b1,
    const float* __restrict__ W2, const float* __restrict__ b2, int N) {
    extern __shared__ float sm[];
    float* W1s  = sm;                 // 4096
    float* W2s  = sm + 4096;          // 4096
    float* b1s  = sm + 8192;          // 64
    float* b2s  = sm + 8256;          // 64
    float* rows = sm + 8320;          // 128 * 65

    int tid  = threadIdx.x;
    int node = blockIdx.x * 128 + tid;

    for (int i = tid; i < 4096; i += 128) {
        W1s[i] = W1[i];
        W2s[i] = W2[i];
    }
    if (tid < 64) {
        b1s[tid] = b1[tid];
        b2s[tid] = b2[tid];
    }

    float* myrow = rows + tid * 65;
    if (node < N) {
        const float4* h4 = reinterpret_cast<const float4*>(hin);
#pragma unroll
        for (int c = 0; c < 16; c++) {
            float4 v = h4[node * 16 + c];
            myrow[4 * c + 0] = v.x;
            myrow[4 * c + 1] = v.y;
            myrow[4 * c + 2] = v.z;
            myrow[4 * c + 3] = v.w;
        }
    } else {
#pragma unroll
        for (int c = 0; c < DIM; c++) myrow[c] = 0.0f;
    }
    __syncthreads();

    if (node < N) {
        mlp_stage(myrow, W1s, b1s);
        mlp_stage(myrow, W2s, b2s);
    }
    __syncthreads();

    // coalesced store of h to global
    int base = blockIdx.x * 128 * DIM;
    for (int i = tid; i < 128 * DIM; i += 128) {
        int r = i >> 6, c = i & 63;
        if (blockIdx.x * 128 + r < N) g_h[base + i] = rows[r * 65 + c];
    }

    // block-level BN statistics (invalid rows are zero -> contribute nothing)
    if (tid < 64) {
        float s = 0.0f;
        for (int r = 0; r < 128; r++) s += rows[r * 65 + tid];
        atomicAdd(&g_stats[tid], s);
    } else {
        int j = tid - 64;
        float s = 0.0f;
        for (int r = 0; r < 128; r++) {
            float v = rows[r * 65 + j];
            s += v * v;
        }
        atomicAdd(&g_stats[64 + j], s);
    }
}

// ---------------- BN finalize ----------------------------------------------
__global__ void finalize_kernel(const float* __restrict__ gamma,
                                const float* __restrict__ beta, float invN) {
    int j = threadIdx.x;  // 64 threads
    float mean = g_stats[j] * invN;
    float var  = g_stats[64 + j] * invN - mean * mean;
    float sc   = gamma[j] * rsqrtf(var + BN_EPS);
    g_scale[j] = sc;
    g_shift[j] = beta[j] - mean * sc;
}

// ---------------- BN apply + segmented pool (batch is sorted) --------------
__global__ __launch_bounds__(64) void pool_kernel(
    const int* __restrict__ batch, float* __restrict__ out,
    float* __restrict__ xstore, int col_off, int N) {
    int t = threadIdx.x;  // 64 = one column each
    int n0 = blockIdx.x * POOL_CH;
    int n1 = n0 + POOL_CH;
    if (n1 > N) n1 = N;
    float sc = g_scale[t];
    float sh = g_shift[t];
    int cur = __ldg(batch + n0);
    float acc = 0.0f;
    for (int n = n0; n < n1; n++) {
        int g = __ldg(batch + n);
        float v = g_h[n * DIM + t] * sc + sh;
        if (xstore) xstore[n * DIM + t] = v;
        if (g != cur) {
            atomicAdd(&out[cur * 128 + col_off + t], acc);
            acc = 0.0f;
            cur = g;
        }
        acc += v;
    }
    atomicAdd(&out[cur * 128 + col_off + t], acc);
}

// ---------------------------------------------------------------------------
extern "C" void kernel_launch(void* const* d_in, const int* in_sizes, int n_in,
                              void* d_out, int out_size) {
    const float* x       = (const float*)d_in[0];
    const float* W1_0    = (const float*)d_in[1];
    const float* b1_0    = (const float*)d_in[2];
    const float* W2_0    = (const float*)d_in[3];
    const float* b2_0    = (const float*)d_in[4];
    const float* gamma_0 = (const float*)d_in[5];
    const float* beta_0  = (const float*)d_in[6];
    const float* W1_1    = (const float*)d_in[7];
    const float* b1_1    = (const float*)d_in[8];
    const float* W2_1    = (const float*)d_in[9];
    const float* b2_1    = (const float*)d_in[10];
    const float* gamma_1 = (const float*)d_in[11];
    const float* beta_1  = (const float*)d_in[12];
    const int*   ei      = (const int*)d_in[13];
    const int*   batch   = (const int*)d_in[14];

    int N = in_sizes[0] / DIM;
    int E = in_sizes[13] / 2;
    float* out = (float*)d_out;

    void *stats_p, *x0_p, *hin_p, *cursor_p;
    cudaGetSymbolAddress(&stats_p, g_stats);
    cudaGetSymbolAddress(&x0_p, g_x0);
    cudaGetSymbolAddress(&hin_p, g_hin);
    cudaGetSymbolAddress(&cursor_p, g_cursor);

    cudaFuncSetAttribute(mlp_kernel,
                         cudaFuncAttributeMaxDynamicSharedMemorySize,
                         MLP_SMEM_BYTES);

    int edge_blocks = (E + 255) / 256;
    int nb_scan     = (N + SCAN_BS - 1) / SCAN_BS;
    int agg_blocks  = (N + 7) / 8;
    int mlp_blocks  = (N + 127) / 128;
    int pool_blocks = (N + POOL_CH - 1) / POOL_CH;
    float invN = 1.0f / (float)N;

    cudaMemsetAsync(out, 0, (size_t)out_size * sizeof(float));

    // ---- CSR build (shared by both layers) ----
    cudaMemsetAsync(cursor_p, 0, (size_t)(N + 1) * sizeof(int));
    hist_kernel<<<edge_blocks, 256>>>(ei, E);
    reduce_kernel<<<nb_scan, SCAN_BS>>>(N);
    scan_bsums_kernel<<<1, 1>>>(nb_scan);
    scan_final_kernel<<<nb_scan, SCAN_BS>>>(N);
    fill_kernel<<<edge_blocks, 256>>>(ei, E);

    // ---------------- layer 0 ----------------
    aggregate_kernel<<<agg_blocks, 128>>>(x, (float*)hin_p, N);
    cudaMemsetAsync(stats_p, 0, 2 * DIM * sizeof(float));
    mlp_kernel<<<mlp_blocks, 128, MLP_SMEM_BYTES>>>((const float*)hin_p,
                                                    W1_0, b1_0, W2_0, b2_0, N);
    finalize_kernel<<<1, 64>>>(gamma_0, beta_0, invN);
    pool_kernel<<<pool_blocks, 64>>>(batch, out, (float*)x0_p, 0, N);

    // ---------------- layer 1 ----------------
    aggregate_kernel<<<agg_blocks, 128>>>((const float*)x0_p, (float*)hin_p, N);
    cudaMemsetAsync(stats_p, 0, 2 * DIM * sizeof(float));
    mlp_kernel<<<mlp_blocks, 128, MLP_SMEM_BYTES>>>((const float*)hin_p,
                                                    W1_1, b1_1, W2_1, b2_1, N);
    finalize_kernel<<<1, 64>>>(gamma_1, beta_1, invN);
    pool_kernel<<<pool_blocks, 64>>>(batch, out, nullptr, 64, N);
}